// round 1
// baseline (speedup 1.0000x reference)
#include <cuda_runtime.h>
#include <cuda_bf16.h>

// SetAbstraction fused kernel (fp32 baseline).
// One CTA handles MB=2 query points (64 neighbor-rows total).
// Pipeline fully fused in shared memory:
//   gather -> L1(67->128)+LN+ReLU -> L2(128->128)+LN+ReLU -> L3(128->256)+LN+ReLU
//   -> attention scores (259->256 relu -> dot Wa2) -> softmax over K
//   -> weighted sum -> Wo projection (256->256)

#define NTHREADS 256
#define MB 2            // query points per block
#define KNB 32          // neighbors per query
#define ROWS (MB*KNB)   // 64
#define RPW 8           // rows per warp (8 warps * 8 = 64)
#define CT 32           // weight-chunk rows staged in smem

__device__ __forceinline__ float warp_sum(float v) {
#pragma unroll
    for (int o = 16; o > 0; o >>= 1) v += __shfl_xor_sync(0xffffffffu, v, o);
    return v;
}

// Y[64][FO] = relu(LayerNorm(X[64][FI] @ W + b) * g + be)
// Row r handled entirely by warp r/8; lane owns FO/32 contiguous columns.
template <int FO>
__device__ void layer_ln(const float* Xs, int ldx, int FI,
                         const float* __restrict__ W, const float* __restrict__ b,
                         const float* __restrict__ g, const float* __restrict__ be,
                         float* Ys, float* Wc) {
    constexpr int J = FO / 32;
    const int tid  = threadIdx.x;
    const int lane = tid & 31;
    const int warp = tid >> 5;
    const int r0   = warp * RPW;
    const int col0 = lane * J;

    float acc[RPW][J];
#pragma unroll
    for (int r = 0; r < RPW; r++)
#pragma unroll
        for (int j = 0; j < J; j++) acc[r][j] = 0.f;

    for (int c0 = 0; c0 < FI; c0 += CT) {
        int cn = FI - c0; if (cn > CT) cn = CT;
        __syncthreads();   // prev consumers of Wc / producers of Xs done
        const float* Wsrc = W + (size_t)c0 * FO;
        for (int i = tid; i < cn * FO; i += NTHREADS) Wc[i] = Wsrc[i];
        __syncthreads();
#pragma unroll 4
        for (int c = 0; c < cn; c++) {
            float w[J];
#pragma unroll
            for (int j4 = 0; j4 < J; j4 += 4) {
                float4 v = *reinterpret_cast<const float4*>(Wc + c * FO + col0 + j4);
                w[j4] = v.x; w[j4+1] = v.y; w[j4+2] = v.z; w[j4+3] = v.w;
            }
#pragma unroll
            for (int r = 0; r < RPW; r++) {
                float x = Xs[(r0 + r) * ldx + c0 + c];
#pragma unroll
                for (int j = 0; j < J; j++) acc[r][j] = fmaf(x, w[j], acc[r][j]);
            }
        }
    }

    float bc[J], gc[J], bec[J];
#pragma unroll
    for (int j = 0; j < J; j++) { bc[j] = b[col0+j]; gc[j] = g[col0+j]; bec[j] = be[col0+j]; }
    const float invFO = 1.0f / (float)FO;
#pragma unroll
    for (int r = 0; r < RPW; r++) {
        float s = 0.f, s2 = 0.f;
#pragma unroll
        for (int j = 0; j < J; j++) {
            float v = acc[r][j] + bc[j];
            acc[r][j] = v; s += v; s2 += v * v;
        }
        s  = warp_sum(s);
        s2 = warp_sum(s2);
        float mean = s * invFO;
        float var  = s2 * invFO - mean * mean;
        float inv  = rsqrtf(var + 1e-5f);
#pragma unroll
        for (int j = 0; j < J; j++) {
            float v = (acc[r][j] - mean) * inv * gc[j] + bec[j];
            acc[r][j] = fmaxf(v, 0.f);
        }
#pragma unroll
        for (int j4 = 0; j4 < J; j4 += 4) {
            float4 v;
            v.x = acc[r][j4]; v.y = acc[r][j4+1]; v.z = acc[r][j4+2]; v.w = acc[r][j4+3];
            *reinterpret_cast<float4*>(Ys + (r0 + r) * FO + col0 + j4) = v;
        }
    }
}

// scores[r] = relu([rel_r, h3_r] @ Wa1 + ba1) @ Wa2 + ba2   (FI=259, FO=256)
__device__ void attn_scores(const float* X0s, const float* H3s,
                            const float* __restrict__ Wa1, const float* __restrict__ ba1,
                            const float* __restrict__ Wa2, const float* __restrict__ ba2,
                            float* scores, float* Wc) {
    constexpr int FO = 256, J = 8, FI = 259;
    const int tid  = threadIdx.x;
    const int lane = tid & 31;
    const int warp = tid >> 5;
    const int r0   = warp * RPW;
    const int col0 = lane * J;

    float acc[RPW][J];
#pragma unroll
    for (int r = 0; r < RPW; r++)
#pragma unroll
        for (int j = 0; j < J; j++) acc[r][j] = 0.f;

    for (int c0 = 0; c0 < FI; c0 += CT) {
        int cn = FI - c0; if (cn > CT) cn = CT;
        __syncthreads();
        const float* Wsrc = Wa1 + (size_t)c0 * FO;
        for (int i = tid; i < cn * FO; i += NTHREADS) Wc[i] = Wsrc[i];
        __syncthreads();
#pragma unroll 4
        for (int c = 0; c < cn; c++) {
            int cg = c0 + c;
            float w[J];
#pragma unroll
            for (int j4 = 0; j4 < J; j4 += 4) {
                float4 v = *reinterpret_cast<const float4*>(Wc + c * FO + col0 + j4);
                w[j4] = v.x; w[j4+1] = v.y; w[j4+2] = v.z; w[j4+3] = v.w;
            }
#pragma unroll
            for (int r = 0; r < RPW; r++) {
                float x = (cg < 3) ? X0s[(r0 + r) * 68 + cg]
                                   : H3s[(r0 + r) * 256 + (cg - 3)];
#pragma unroll
                for (int j = 0; j < J; j++) acc[r][j] = fmaf(x, w[j], acc[r][j]);
            }
        }
    }

    float bc[J], a2[J];
#pragma unroll
    for (int j = 0; j < J; j++) { bc[j] = ba1[col0+j]; a2[j] = Wa2[col0+j]; }
    const float bb = ba2[0];
#pragma unroll
    for (int r = 0; r < RPW; r++) {
        float sc = 0.f;
#pragma unroll
        for (int j = 0; j < J; j++)
            sc += fmaxf(acc[r][j] + bc[j], 0.f) * a2[j];
        sc = warp_sum(sc);
        if (lane == 0) scores[r0 + r] = sc + bb;
    }
}

extern __shared__ float smem[];

__global__ __launch_bounds__(NTHREADS)
void sa_fused_kernel(const float* __restrict__ xyz, const float* __restrict__ feat,
                     const int* __restrict__ scanidx, const int* __restrict__ group_idx,
                     const float* __restrict__ W1, const float* __restrict__ b1,
                     const float* __restrict__ g1, const float* __restrict__ be1,
                     const float* __restrict__ W2, const float* __restrict__ b2,
                     const float* __restrict__ g2, const float* __restrict__ be2,
                     const float* __restrict__ W3, const float* __restrict__ b3,
                     const float* __restrict__ g3, const float* __restrict__ be3,
                     const float* __restrict__ Wa1, const float* __restrict__ ba1,
                     const float* __restrict__ Wa2, const float* __restrict__ ba2,
                     const float* __restrict__ Wo, const float* __restrict__ bo,
                     float* __restrict__ out_xyz, float* __restrict__ out_feat) {
    // SMEM layout (floats)
    float* X0s    = smem;                 // 64*68  = 4352
    float* H1s    = X0s + ROWS * 68;      // 64*128 = 8192
    float* H2s    = H1s + ROWS * 128;     // 8192
    float* H3s    = H2s + ROWS * 128;     // 64*256 = 16384
    float* Wc     = H3s + ROWS * 256;     // 32*256 = 8192
    float* scores = Wc + CT * 256;        // 64
    float* wgt    = scores + ROWS;        // 64
    float* wsum   = wgt + ROWS;           // 2*256
    int*   gidx   = (int*)(wsum + MB * 256);  // 64 ints

    const int tid = threadIdx.x;
    const int m0  = blockIdx.x * MB;

    // ---- gather: rel + features into X0s [64][68] (cols 0..2 = rel, 3..66 = feat)
    if (tid < ROWS) {
        int mi = tid >> 5, k = tid & 31;
        int g = group_idx[(size_t)(m0 + mi) * KNB + k];
        gidx[tid] = g;
        int s = scanidx[m0 + mi];
#pragma unroll
        for (int d = 0; d < 3; d++)
            X0s[tid * 68 + d] = xyz[(size_t)g * 3 + d] - xyz[(size_t)s * 3 + d];
    }
    __syncthreads();
    const float4* feat4 = reinterpret_cast<const float4*>(feat);
    for (int i = tid; i < ROWS * 16; i += NTHREADS) {
        int r = i >> 4, c = i & 15;
        float4 v = feat4[(size_t)gidx[r] * 16 + c];
        float* dst = X0s + r * 68 + 3 + c * 4;
        dst[0] = v.x; dst[1] = v.y; dst[2] = v.z; dst[3] = v.w;
    }
    // (layer_ln's leading __syncthreads orders these writes)

    // ---- MLP stack
    layer_ln<128>(X0s, 68, 67,  W1, b1, g1, be1, H1s, Wc);
    layer_ln<128>(H1s, 128, 128, W2, b2, g2, be2, H2s, Wc);
    layer_ln<256>(H2s, 128, 128, W3, b3, g3, be3, H3s, Wc);

    // ---- attention scores
    attn_scores(X0s, H3s, Wa1, ba1, Wa2, ba2, scores, Wc);
    __syncthreads();

    // ---- softmax over K (one warp per query point)
    const int lane = tid & 31, warp = tid >> 5;
    if (warp < MB) {
        float v = scores[warp * KNB + lane];
        float mx = v;
#pragma unroll
        for (int o = 16; o > 0; o >>= 1) mx = fmaxf(mx, __shfl_xor_sync(0xffffffffu, mx, o));
        float e = __expf(v - mx);
        float s = warp_sum(e);
        wgt[warp * KNB + lane] = e / s;
    }
    __syncthreads();

    // ---- weighted sum over K: wsum[mi][c] = sum_k wgt * h3
    {
        int c = tid;   // 0..255
        float a0 = 0.f, a1 = 0.f;
#pragma unroll 8
        for (int k = 0; k < KNB; k++) {
            a0 = fmaf(wgt[k],       H3s[k * 256 + c],          a0);
            a1 = fmaf(wgt[KNB + k], H3s[(KNB + k) * 256 + c],  a1);
        }
        wsum[c] = a0; wsum[256 + c] = a1;
    }
    __syncthreads();

    // ---- output projection: out = wsum @ Wo + bo
    {
        int c = tid;
        float o0 = bo[c], o1 = o0;
#pragma unroll 4
        for (int k = 0; k < 256; k++) {
            float wv = Wo[(size_t)k * 256 + c];
            o0 = fmaf(wsum[k],       wv, o0);
            o1 = fmaf(wsum[256 + k], wv, o1);
        }
        out_feat[(size_t)m0 * 256 + c]       = o0;
        out_feat[(size_t)(m0 + 1) * 256 + c] = o1;
    }

    // ---- new_xyz output
    if (out_xyz != nullptr && tid < MB * 3) {
        int mi = tid / 3, d = tid % 3;
        int s = scanidx[m0 + mi];
        out_xyz[(size_t)(m0 + mi) * 3 + d] = xyz[(size_t)s * 3 + d];
    }
}

extern "C" void kernel_launch(void* const* d_in, const int* in_sizes, int n_in,
                              void* d_out, int out_size) {
    const float* xyz       = (const float*)d_in[0];
    const float* feat      = (const float*)d_in[1];
    const int*   scanidx   = (const int*)d_in[2];
    const int*   group_idx = (const int*)d_in[3];
    const float* W1  = (const float*)d_in[4];
    const float* b1  = (const float*)d_in[5];
    const float* g1  = (const float*)d_in[6];
    const float* be1 = (const float*)d_in[7];
    const float* W2  = (const float*)d_in[8];
    const float* b2  = (const float*)d_in[9];
    const float* g2  = (const float*)d_in[10];
    const float* be2 = (const float*)d_in[11];
    const float* W3  = (const float*)d_in[12];
    const float* b3  = (const float*)d_in[13];
    const float* g3  = (const float*)d_in[14];
    const float* be3 = (const float*)d_in[15];
    const float* Wa1 = (const float*)d_in[16];
    const float* ba1 = (const float*)d_in[17];
    const float* Wa2 = (const float*)d_in[18];
    const float* ba2 = (const float*)d_in[19];
    const float* Wo  = (const float*)d_in[20];
    const float* bo  = (const float*)d_in[21];

    const int M = in_sizes[2];

    // Output layout: tuple (new_xyz[M,3], out[M,256]) flattened in order.
    float* out_xyz  = nullptr;
    float* out_feat = (float*)d_out;
    if (out_size == M * 259) {
        out_xyz  = (float*)d_out;
        out_feat = (float*)d_out + (size_t)M * 3;
    }

    const size_t smem_bytes =
        (ROWS * 68 + ROWS * 128 * 2 + ROWS * 256 + CT * 256 + ROWS * 2 + MB * 256) * sizeof(float)
        + ROWS * sizeof(int);

    cudaFuncSetAttribute(sa_fused_kernel,
                         cudaFuncAttributeMaxDynamicSharedMemorySize, (int)smem_bytes);

    sa_fused_kernel<<<M / MB, NTHREADS, smem_bytes>>>(
        xyz, feat, scanidx, group_idx,
        W1, b1, g1, be1, W2, b2, g2, be2, W3, b3, g3, be3,
        Wa1, ba1, Wa2, ba2, Wo, bo,
        out_xyz, out_feat);
}

// round 2
// speedup vs baseline: 1.3825x; 1.3825x over previous
#include <cuda_runtime.h>
#include <cstdint>

// SetAbstraction fused kernel, round 2: packed f32x2 FMA + cp.async double-buffered
// weight staging + conflict-free SMEM layout. One CTA = 2 query points (64 rows).

#define NT 256
#define MB 2
#define KNB 32
#define ROWS 64          // MB*KNB
#define RPW 8            // rows per warp (8 warps)
#define CT 32            // weight rows per staged chunk
#define LDX0 96          // padded stride of X0 (67 real cols -> 96)

typedef unsigned long long ull;

__device__ __forceinline__ ull pk2(float a, float b) {
    ull r; asm("mov.b64 %0,{%1,%2};" : "=l"(r) : "f"(a), "f"(b)); return r;
}
__device__ __forceinline__ void up2(ull v, float& a, float& b) {
    asm("mov.b64 {%0,%1},%2;" : "=f"(a), "=f"(b) : "l"(v));
}
__device__ __forceinline__ ull add2(ull a, ull b) {
    ull r; asm("add.rn.f32x2 %0,%1,%2;" : "=l"(r) : "l"(a), "l"(b)); return r;
}
__device__ __forceinline__ void fma2(ull& d, ull a, ull b) {
    asm("fma.rn.f32x2 %0,%1,%2,%0;" : "+l"(d) : "l"(a), "l"(b));
}
__device__ __forceinline__ ull fma2r(ull a, ull b, ull c) {
    ull r; asm("fma.rn.f32x2 %0,%1,%2,%3;" : "=l"(r) : "l"(a), "l"(b), "l"(c)); return r;
}

#define CP_COMMIT asm volatile("cp.async.commit_group;")
#define CP_WAIT0  asm volatile("cp.async.wait_group 0;")

__device__ __forceinline__ void cpa16(float* dst, const float* src) {
    unsigned d = (unsigned)__cvta_generic_to_shared(dst);
    asm volatile("cp.async.ca.shared.global [%0], [%1], 16;" :: "r"(d), "l"(src));
}

__device__ __forceinline__ float warp_sum(float v) {
#pragma unroll
    for (int o = 16; o > 0; o >>= 1) v += __shfl_xor_sync(0xffffffffu, v, o);
    return v;
}

// Stage CT rows x FO cols of W (rows >= FI zero-filled) into smem buf via cp.async.
template <int FO>
__device__ __forceinline__ void stage(float* buf, const float* __restrict__ W,
                                      int c0, int FI) {
    constexpr int VPR = FO / 4;       // 16B vectors per row
    constexpr int NV  = CT * VPR;
    const int tid = threadIdx.x;
#pragma unroll
    for (int i = tid; i < NV; i += NT) {
        int row = i / VPR;
        int gc  = c0 + row;
        if (gc < FI) cpa16(buf + i * 4, W + (size_t)gc * FO + (i % VPR) * 4);
        else         *reinterpret_cast<float4*>(buf + i * 4) = make_float4(0.f, 0.f, 0.f, 0.f);
    }
}

// acc[r][NB*2] packed col-pairs. Lane owns cols {blk*128 + lane*4 .. +3} per block.
template <int FO>
__device__ __forceinline__ void gemm_chunk(const float* Xs, int ldx, int c0,
                                           const float* Wc, ull (*acc)[FO / 64]) {
    constexpr int NB = FO / 128;
    const int lane = threadIdx.x & 31, warp = threadIdx.x >> 5;
    const int r0 = warp * RPW;
    const float* wbase = Wc + lane * 4;
#pragma unroll 4
    for (int c = 0; c < CT; c += 4) {
        float4 xv[RPW];
#pragma unroll
        for (int r = 0; r < RPW; r++)
            xv[r] = *reinterpret_cast<const float4*>(Xs + (r0 + r) * ldx + c0 + c);
#pragma unroll
        for (int cc = 0; cc < 4; cc++) {
            ull w[NB][2];
#pragma unroll
            for (int b = 0; b < NB; b++) {
                ulonglong2 wv = *reinterpret_cast<const ulonglong2*>(wbase + (c + cc) * FO + b * 128);
                w[b][0] = wv.x; w[b][1] = wv.y;
            }
#pragma unroll
            for (int r = 0; r < RPW; r++) {
                float x = (cc == 0) ? xv[r].x : (cc == 1) ? xv[r].y : (cc == 2) ? xv[r].z : xv[r].w;
                ull xd = pk2(x, x);
#pragma unroll
                for (int b = 0; b < NB; b++) {
                    fma2(acc[r][b * 2 + 0], xd, w[b][0]);
                    fma2(acc[r][b * 2 + 1], xd, w[b][1]);
                }
            }
        }
    }
}

// LayerNorm + ReLU epilogue; stores float4 (conflict-free).
template <int FO>
__device__ __forceinline__ void ln_epi(ull (*acc)[FO / 64],
                                       const float* __restrict__ b, const float* __restrict__ g,
                                       const float* __restrict__ be, float* Ys) {
    constexpr int NB = FO / 128;
    const int lane = threadIdx.x & 31, warp = threadIdx.x >> 5;
    const int r0 = warp * RPW;
    ull bp[NB][2], gp[NB][2], bep[NB][2];
#pragma unroll
    for (int bb = 0; bb < NB; bb++) {
        ulonglong2 t;
        t = *reinterpret_cast<const ulonglong2*>(b  + bb * 128 + lane * 4); bp[bb][0] = t.x; bp[bb][1] = t.y;
        t = *reinterpret_cast<const ulonglong2*>(g  + bb * 128 + lane * 4); gp[bb][0] = t.x; gp[bb][1] = t.y;
        t = *reinterpret_cast<const ulonglong2*>(be + bb * 128 + lane * 4); bep[bb][0] = t.x; bep[bb][1] = t.y;
    }
    const float invFO = 1.f / (float)FO;
#pragma unroll
    for (int r = 0; r < RPW; r++) {
        ull s = 0ull, q = 0ull;
#pragma unroll
        for (int bb = 0; bb < NB; bb++)
#pragma unroll
            for (int p = 0; p < 2; p++) {
                ull v = add2(acc[r][bb * 2 + p], bp[bb][p]);
                acc[r][bb * 2 + p] = v;
                s = add2(s, v);
                q = fma2r(v, v, q);
            }
        float sl, sh, ql, qh; up2(s, sl, sh); up2(q, ql, qh);
        ull sq = pk2(sl + sh, ql + qh);
#pragma unroll
        for (int o = 16; o > 0; o >>= 1) sq = add2(sq, __shfl_xor_sync(0xffffffffu, sq, o));
        float S, Q; up2(sq, S, Q);
        float mean = S * invFO;
        float var  = fmaxf(Q * invFO - mean * mean, 0.f);
        float inv  = rsqrtf(var + 1e-5f);
        ull vInv = pk2(inv, inv), vOff = pk2(-mean * inv, -mean * inv);
#pragma unroll
        for (int bb = 0; bb < NB; bb++) {
            ull t0 = fma2r(fma2r(acc[r][bb * 2 + 0], vInv, vOff), gp[bb][0], bep[bb][0]);
            ull t1 = fma2r(fma2r(acc[r][bb * 2 + 1], vInv, vOff), gp[bb][1], bep[bb][1]);
            float4 o;
            up2(t0, o.x, o.y); up2(t1, o.z, o.w);
            o.x = fmaxf(o.x, 0.f); o.y = fmaxf(o.y, 0.f);
            o.z = fmaxf(o.z, 0.f); o.w = fmaxf(o.w, 0.f);
            *reinterpret_cast<float4*>(Ys + (r0 + r) * FO + bb * 128 + lane * 4) = o;
        }
    }
}

extern __shared__ float smem[];

__global__ __launch_bounds__(NT, 1)
void sa_fused_kernel(const float* __restrict__ xyz, const float* __restrict__ feat,
                     const int* __restrict__ scanidx, const int* __restrict__ group_idx,
                     const float* __restrict__ W1, const float* __restrict__ b1,
                     const float* __restrict__ g1, const float* __restrict__ be1,
                     const float* __restrict__ W2, const float* __restrict__ b2,
                     const float* __restrict__ g2, const float* __restrict__ be2,
                     const float* __restrict__ W3, const float* __restrict__ b3,
                     const float* __restrict__ g3, const float* __restrict__ be3,
                     const float* __restrict__ Wa1, const float* __restrict__ ba1,
                     const float* __restrict__ Wa2, const float* __restrict__ ba2,
                     const float* __restrict__ Wo, const float* __restrict__ bo,
                     float* __restrict__ out_xyz, float* __restrict__ out_feat) {
    float* X0s    = smem;                        // 64*96
    float* H12s   = X0s + ROWS * LDX0;           // 64*128 (H1 then H2 in place)
    float* H3s    = H12s + ROWS * 128;           // 64*256
    float* Wc0    = H3s + ROWS * 256;            // 32*256
    float* Wc1    = Wc0 + CT * 256;              // 32*256
    float* scores = Wc1 + CT * 256;              // 64
    float* wgt    = scores + ROWS;               // 64
    float* wsum   = wgt + ROWS;                  // 2*256
    int*   gidx   = (int*)(wsum + MB * 256);     // 64

    float* WcB[2] = { Wc0, Wc1 };

    const int tid  = threadIdx.x;
    const int lane = tid & 31, warp = tid >> 5;
    const int r0   = warp * RPW;
    const int m0   = blockIdx.x * MB;

    // Prefetch L1 chunk 0 immediately (overlaps with gather).
    stage<128>(WcB[0], W1, 0, 67);
    CP_COMMIT;

    // ---- gather phase ----
    for (int i = tid; i < ROWS * LDX0; i += NT) X0s[i] = 0.f;
    if (tid < ROWS) gidx[tid] = group_idx[(size_t)(m0 + (tid >> 5)) * KNB + (tid & 31)];
    __syncthreads();
    if (tid < ROWS) {
        int g = gidx[tid];
        int s = scanidx[m0 + (tid >> 5)];
#pragma unroll
        for (int d = 0; d < 3; d++)
            X0s[tid * LDX0 + d] = xyz[(size_t)g * 3 + d] - xyz[(size_t)s * 3 + d];
    }
    const float4* feat4 = reinterpret_cast<const float4*>(feat);
    for (int i = tid; i < ROWS * 16; i += NT) {
        int r = i & 63, c = i >> 6;
        float4 v = feat4[(size_t)gidx[r] * 16 + c];
        float* dst = X0s + r * LDX0 + 3 + c * 4;
        dst[0] = v.x; dst[1] = v.y; dst[2] = v.z; dst[3] = v.w;
    }
    // first chunk-loop __syncthreads orders gather before compute

    // ---- L1: 67 -> 128 (3 chunks, global idx 0..2) ----
    {
        ull acc[RPW][2];
#pragma unroll
        for (int r = 0; r < RPW; r++) { acc[r][0] = 0ull; acc[r][1] = 0ull; }
        for (int ch = 0; ch < 3; ch++) {
            CP_WAIT0; __syncthreads();
            if (ch == 0)      stage<128>(WcB[1], W1, 32, 67);
            else if (ch == 1) stage<128>(WcB[0], W1, 64, 67);
            else              stage<128>(WcB[1], W2, 0, 128);
            CP_COMMIT;
            gemm_chunk<128>(X0s, LDX0, ch * CT, WcB[ch & 1], acc);
        }
        ln_epi<128>(acc, b1, g1, be1, H12s);
    }
    // ---- L2: 128 -> 128 (chunks idx 3..6; buffers continue parity) ----
    {
        ull acc[RPW][2];
#pragma unroll
        for (int r = 0; r < RPW; r++) { acc[r][0] = 0ull; acc[r][1] = 0ull; }
        for (int ch = 0; ch < 4; ch++) {
            CP_WAIT0; __syncthreads();
            if (ch < 3) stage<128>(WcB[(4 + ch) & 1], W2, (ch + 1) * CT, 128);
            else        stage<256>(WcB[(4 + ch) & 1], W3, 0, 128);
            CP_COMMIT;
            gemm_chunk<128>(H12s, 128, ch * CT, WcB[(3 + ch) & 1], acc);
        }
        ln_epi<128>(acc, b2, g2, be2, H12s);  // in place H1 -> H2 (warp-private rows)
    }
    // ---- L3: 128 -> 256 (chunks idx 7..10) ----
    ull acc3[RPW][4];
    {
#pragma unroll
        for (int r = 0; r < RPW; r++)
#pragma unroll
            for (int p = 0; p < 4; p++) acc3[r][p] = 0ull;
        for (int ch = 0; ch < 4; ch++) {
            CP_WAIT0; __syncthreads();
            if (ch < 3) stage<256>(WcB[(8 + ch) & 1], W3, (ch + 1) * CT, 128);
            else        stage<256>(WcB[(8 + ch) & 1], Wa1 + 3 * 256, 0, 256);
            CP_COMMIT;
            gemm_chunk<256>(H12s, 128, ch * CT, WcB[(7 + ch) & 1], acc3);
        }
        ln_epi<256>(acc3, b3, g3, be3, H3s);
    }
    // ---- attention: score = relu([rel,h3] @ Wa1 + ba1) . Wa2 + ba2 ----
    {
#pragma unroll
        for (int r = 0; r < RPW; r++)
#pragma unroll
            for (int p = 0; p < 4; p++) acc3[r][p] = 0ull;
        // rel part (3 cols), weights direct from global (L2-resident)
#pragma unroll
        for (int c = 0; c < 3; c++) {
            ull w[2][2];
#pragma unroll
            for (int b = 0; b < 2; b++) {
                ulonglong2 wv = *reinterpret_cast<const ulonglong2*>(Wa1 + c * 256 + b * 128 + lane * 4);
                w[b][0] = wv.x; w[b][1] = wv.y;
            }
#pragma unroll
            for (int r = 0; r < RPW; r++) {
                float x = X0s[(r0 + r) * LDX0 + c];
                ull xd = pk2(x, x);
#pragma unroll
                for (int b = 0; b < 2; b++) {
                    fma2(acc3[r][b * 2 + 0], xd, w[b][0]);
                    fma2(acc3[r][b * 2 + 1], xd, w[b][1]);
                }
            }
        }
        // h3 part (chunks idx 11..18)
        for (int ch = 0; ch < 8; ch++) {
            CP_WAIT0; __syncthreads();
            if (ch < 7) { stage<256>(WcB[(12 + ch) & 1], Wa1 + 3 * 256, (ch + 1) * CT, 256); CP_COMMIT; }
            gemm_chunk<256>(H3s, 256, ch * CT, WcB[(11 + ch) & 1], acc3);
        }
        // epilogue: relu + dot with Wa2
        ull bp[2][2], ap[2][2];
#pragma unroll
        for (int b = 0; b < 2; b++) {
            ulonglong2 t;
            t = *reinterpret_cast<const ulonglong2*>(ba1 + b * 128 + lane * 4); bp[b][0] = t.x; bp[b][1] = t.y;
            t = *reinterpret_cast<const ulonglong2*>(Wa2 + b * 128 + lane * 4); ap[b][0] = t.x; ap[b][1] = t.y;
        }
        const float bb2 = ba2[0];
#pragma unroll
        for (int r = 0; r < RPW; r++) {
            float sc = 0.f;
#pragma unroll
            for (int b = 0; b < 2; b++)
#pragma unroll
                for (int p = 0; p < 2; p++) {
                    float vl, vh, al, ah;
                    up2(add2(acc3[r][b * 2 + p], bp[b][p]), vl, vh);
                    up2(ap[b][p], al, ah);
                    sc = fmaf(fmaxf(vl, 0.f), al, sc);
                    sc = fmaf(fmaxf(vh, 0.f), ah, sc);
                }
            sc = warp_sum(sc);
            if (lane == 0) scores[r0 + r] = sc + bb2;
        }
    }
    __syncthreads();

    // ---- softmax over K (warp 0,1 -> query 0,1) ----
    if (warp < MB) {
        float v = scores[warp * KNB + lane];
        float mx = v;
#pragma unroll
        for (int o = 16; o > 0; o >>= 1) mx = fmaxf(mx, __shfl_xor_sync(0xffffffffu, mx, o));
        float e = __expf(v - mx);
        float s = warp_sum(e);
        wgt[warp * KNB + lane] = e / s;
    }
    __syncthreads();

    // ---- weighted sum over K ----
    {
        int c = tid;
        float a0 = 0.f, a1 = 0.f;
#pragma unroll 8
        for (int k = 0; k < KNB; k++) {
            a0 = fmaf(wgt[k],       H3s[k * 256 + c],         a0);
            a1 = fmaf(wgt[KNB + k], H3s[(KNB + k) * 256 + c], a1);
        }
        wsum[c] = a0; wsum[256 + c] = a1;
    }
    __syncthreads();

    // ---- output projection ----
    {
        int c = tid;
        float o0 = bo[c], o1 = o0;
#pragma unroll 4
        for (int k = 0; k < 256; k++) {
            float wv = Wo[(size_t)k * 256 + c];
            o0 = fmaf(wsum[k],       wv, o0);
            o1 = fmaf(wsum[256 + k], wv, o1);
        }
        out_feat[(size_t)m0 * 256 + c]       = o0;
        out_feat[(size_t)(m0 + 1) * 256 + c] = o1;
    }

    if (out_xyz != nullptr && tid < MB * 3) {
        int mi = tid / 3, d = tid % 3;
        int s = scanidx[m0 + mi];
        out_xyz[(size_t)(m0 + mi) * 3 + d] = xyz[(size_t)s * 3 + d];
    }
}

extern "C" void kernel_launch(void* const* d_in, const int* in_sizes, int n_in,
                              void* d_out, int out_size) {
    const float* xyz       = (const float*)d_in[0];
    const float* feat      = (const float*)d_in[1];
    const int*   scanidx   = (const int*)d_in[2];
    const int*   group_idx = (const int*)d_in[3];
    const float* W1  = (const float*)d_in[4];
    const float* b1  = (const float*)d_in[5];
    const float* g1  = (const float*)d_in[6];
    const float* be1 = (const float*)d_in[7];
    const float* W2  = (const float*)d_in[8];
    const float* b2  = (const float*)d_in[9];
    const float* g2  = (const float*)d_in[10];
    const float* be2 = (const float*)d_in[11];
    const float* W3  = (const float*)d_in[12];
    const float* b3  = (const float*)d_in[13];
    const float* g3  = (const float*)d_in[14];
    const float* be3 = (const float*)d_in[15];
    const float* Wa1 = (const float*)d_in[16];
    const float* ba1 = (const float*)d_in[17];
    const float* Wa2 = (const float*)d_in[18];
    const float* ba2 = (const float*)d_in[19];
    const float* Wo  = (const float*)d_in[20];
    const float* bo  = (const float*)d_in[21];

    const int M = in_sizes[2];

    float* out_xyz  = nullptr;
    float* out_feat = (float*)d_out;
    if (out_size == M * 259) {
        out_xyz  = (float*)d_out;
        out_feat = (float*)d_out + (size_t)M * 3;
    }

    const size_t smem_bytes =
        (ROWS * LDX0 + ROWS * 128 + ROWS * 256 + 2 * CT * 256 + ROWS * 2 + MB * 256) * sizeof(float)
        + ROWS * sizeof(int);

    cudaFuncSetAttribute(sa_fused_kernel,
                         cudaFuncAttributeMaxDynamicSharedMemorySize, (int)smem_bytes);

    sa_fused_kernel<<<M / MB, NT, smem_bytes>>>(
        xyz, feat, scanidx, group_idx,
        W1, b1, g1, be1, W2, b2, g2, be2, W3, b3, g3, be3,
        Wa1, ba1, Wa2, ba2, Wo, bo,
        out_xyz, out_feat);
}